// round 1
// baseline (speedup 1.0000x reference)
#include <cuda_runtime.h>

// Flash-attention fp32 baseline for B=4,H=16,S=2048,D=128, scale = 1/0.32 = 3.125
// Grid: (S/BM, B*H). 256 threads/CTA, 1 CTA/SM.

#define BM 128          // query rows per CTA
#define BN 64           // key rows per tile
#define DD 128          // head dim
#define DP 132          // padded smem row stride for Q/K/V tiles (floats)
#define PNP 68          // padded smem row stride for P/scores (floats)
#define NTHREADS 256
#define SEQ 2048
#define SCALE_INV 3.125f

static constexpr int SMEM_FLOATS = BM*DP + BN*DP + BN*DP + BM*PNP + 3*BM;
static constexpr int SMEM_BYTES  = SMEM_FLOATS * 4;   // ~171.5 KB

__global__ __launch_bounds__(NTHREADS, 1)
void fa_fp32_kernel(const float* __restrict__ Qg, const float* __restrict__ Kg,
                    const float* __restrict__ Vg, float* __restrict__ Og) {
    extern __shared__ float sm[];
    float* sQ = sm;                 // [BM][DP]
    float* sK = sQ + BM*DP;         // [BN][DP]
    float* sV = sK + BN*DP;         // [BN][DP]
    float* sP = sV + BN*DP;         // [BM][PNP]
    float* sM = sP + BM*PNP;        // [BM] running max
    float* sL = sM + BM;            // [BM] running denom
    float* sA = sL + BM;            // [BM] rescale alpha

    const int tid = threadIdx.x;
    const int tx  = tid & 15;       // 16 col-groups
    const int ty  = tid >> 4;       // 16 row-groups

    const size_t hoff = (size_t)blockIdx.y * SEQ * DD;
    const float* Qh = Qg + hoff + (size_t)blockIdx.x * BM * DD;
    const float* Kh = Kg + hoff;
    const float* Vh = Vg + hoff;
    float*       Oh = Og + hoff + (size_t)blockIdx.x * BM * DD;

    // ---- load Q tile (coalesced float4, padded smem rows) ----
    for (int i = tid; i < BM * (DD/4); i += NTHREADS) {
        int r  = i >> 5;        // i / 32
        int c4 = i & 31;
        ((float4*)(sQ + r*DP))[c4] = ((const float4*)Qh)[i];
    }
    if (tid < BM) { sM[tid] = -1e30f; sL[tid] = 0.0f; }

    float oacc[8][8];
    #pragma unroll
    for (int i = 0; i < 8; i++)
        #pragma unroll
        for (int j = 0; j < 8; j++) oacc[i][j] = 0.0f;

    __syncthreads();

    for (int kt = 0; kt < SEQ/BN; kt++) {
        // ---- load K,V tiles ----
        const float4* K4 = (const float4*)(Kh + (size_t)kt * BN * DD);
        const float4* V4 = (const float4*)(Vh + (size_t)kt * BN * DD);
        for (int i = tid; i < BN * (DD/4); i += NTHREADS) {
            int r  = i >> 5;
            int c4 = i & 31;
            ((float4*)(sK + r*DP))[c4] = K4[i];
            ((float4*)(sV + r*DP))[c4] = V4[i];
        }
        __syncthreads();

        // ---- S = Q * K^T (thread: rows ty*8+i, cols tx+16*j) ----
        float sacc[8][4];
        #pragma unroll
        for (int i = 0; i < 8; i++)
            #pragma unroll
            for (int j = 0; j < 4; j++) sacc[i][j] = 0.0f;

        #pragma unroll 2
        for (int k0 = 0; k0 < DD; k0 += 4) {
            float4 qv[8];
            #pragma unroll
            for (int i = 0; i < 8; i++)
                qv[i] = *(const float4*)(sQ + (ty*8 + i)*DP + k0);
            float4 kv[4];
            #pragma unroll
            for (int j = 0; j < 4; j++)
                kv[j] = *(const float4*)(sK + (tx + 16*j)*DP + k0);
            #pragma unroll
            for (int i = 0; i < 8; i++)
                #pragma unroll
                for (int j = 0; j < 4; j++) {
                    sacc[i][j] += qv[i].x * kv[j].x;
                    sacc[i][j] += qv[i].y * kv[j].y;
                    sacc[i][j] += qv[i].z * kv[j].z;
                    sacc[i][j] += qv[i].w * kv[j].w;
                }
        }
        #pragma unroll
        for (int i = 0; i < 8; i++)
            #pragma unroll
            for (int j = 0; j < 4; j++)
                sP[(ty*8 + i)*PNP + (tx + 16*j)] = sacc[i][j] * SCALE_INV;
        __syncthreads();

        // ---- online softmax per row (threads 0..127, one row each) ----
        if (tid < BM) {
            float* row = sP + tid*PNP;
            float mo = sM[tid];
            float mx = mo;
            #pragma unroll 8
            for (int j = 0; j < BN; j++) mx = fmaxf(mx, row[j]);
            float alpha = __expf(mo - mx);
            float sum = 0.0f;
            #pragma unroll 8
            for (int j = 0; j < BN; j++) {
                float p = __expf(row[j] - mx);
                row[j] = p;
                sum += p;
            }
            sM[tid] = mx;
            sL[tid] = sL[tid]*alpha + sum;
            sA[tid] = alpha;
        }
        __syncthreads();

        // ---- O = O*alpha + P @ V (thread: rows ty*8+i, cols tx*8..tx*8+7) ----
        float al[8];
        #pragma unroll
        for (int i = 0; i < 8; i++) al[i] = sA[ty*8 + i];
        #pragma unroll
        for (int i = 0; i < 8; i++)
            #pragma unroll
            for (int j = 0; j < 8; j++) oacc[i][j] *= al[i];

        #pragma unroll 2
        for (int kk = 0; kk < BN; kk += 4) {
            float4 p4[8];
            #pragma unroll
            for (int i = 0; i < 8; i++)
                p4[i] = *(const float4*)(sP + (ty*8 + i)*PNP + kk);
            float4 va[4], vb[4];
            #pragma unroll
            for (int t = 0; t < 4; t++) {
                va[t] = *(const float4*)(sV + (kk + t)*DP + tx*8);
                vb[t] = *(const float4*)(sV + (kk + t)*DP + tx*8 + 4);
            }
            #pragma unroll
            for (int i = 0; i < 8; i++) {
                float pv[4] = {p4[i].x, p4[i].y, p4[i].z, p4[i].w};
                #pragma unroll
                for (int t = 0; t < 4; t++) {
                    oacc[i][0] += pv[t] * va[t].x;
                    oacc[i][1] += pv[t] * va[t].y;
                    oacc[i][2] += pv[t] * va[t].z;
                    oacc[i][3] += pv[t] * va[t].w;
                    oacc[i][4] += pv[t] * vb[t].x;
                    oacc[i][5] += pv[t] * vb[t].y;
                    oacc[i][6] += pv[t] * vb[t].z;
                    oacc[i][7] += pv[t] * vb[t].w;
                }
            }
        }
        __syncthreads();
    }

    // ---- finalize: divide by l, write out ----
    float li[8];
    #pragma unroll
    for (int i = 0; i < 8; i++) li[i] = 1.0f / sL[ty*8 + i];
    #pragma unroll
    for (int i = 0; i < 8; i++) {
        float4 o0, o1;
        o0.x = oacc[i][0]*li[i]; o0.y = oacc[i][1]*li[i];
        o0.z = oacc[i][2]*li[i]; o0.w = oacc[i][3]*li[i];
        o1.x = oacc[i][4]*li[i]; o1.y = oacc[i][5]*li[i];
        o1.z = oacc[i][6]*li[i]; o1.w = oacc[i][7]*li[i];
        *(float4*)(Oh + (ty*8 + i)*DD + tx*8)     = o0;
        *(float4*)(Oh + (ty*8 + i)*DD + tx*8 + 4) = o1;
    }
}

extern "C" void kernel_launch(void* const* d_in, const int* in_sizes, int n_in,
                              void* d_out, int out_size) {
    const float* Q = (const float*)d_in[0];
    const float* K = (const float*)d_in[1];
    const float* V = (const float*)d_in[2];
    float* O = (float*)d_out;

    cudaFuncSetAttribute(fa_fp32_kernel,
                         cudaFuncAttributeMaxDynamicSharedMemorySize, SMEM_BYTES);

    dim3 grid(SEQ / BM, 64 /* B*H */);
    fa_fp32_kernel<<<grid, NTHREADS, SMEM_BYTES>>>(Q, K, V, O);
}